// round 8
// baseline (speedup 1.0000x reference)
#include <cuda_runtime.h>
#include <cuda_bf16.h>
#include <cstdint>

// ----------------------------------------------------------------------------
// RadianceRenderer R8: full MLP chained through HMMA m16n8k16 bf16-split.
// Activations never leave registers (D fragments of layer i = A fragments of
// layer i+1). All B operands pre-packed fragment-ordered by prep kernel.
// Block = 1 ray (64 points), 128 threads (warp = 16 points), 3 blocks/SM.
// ----------------------------------------------------------------------------

typedef unsigned long long ull;
typedef unsigned int u32;

// fragment-ordered B operands, uint4 = {hi(k0,k0+1), hi(k0+8,k0+9), lo.., lo..}
// layout: [tile][lane]. Tiles: W2 @0 (8ks*16nt=128), feat @4096 (8ks*3nt=24),
// c1 @4864 (2ks*16nt=32), c2 @5888 (8ks*1nt=8).
__device__ __align__(16) uint4 g_Bf[6144];

__device__ __forceinline__ void cpa16(u32 dst, const void* src) {
    asm volatile("cp.async.ca.shared.global [%0], [%1], 16;" :: "r"(dst), "l"(src));
}
__device__ __forceinline__ void cpa_commit() {
    asm volatile("cp.async.commit_group;" ::: "memory");
}
template <int N>
__device__ __forceinline__ void cpa_wait() {
    asm volatile("cp.async.wait_group %0;" :: "n"(N) : "memory");
}
__device__ __forceinline__ u32 smem_u32(const void* p) {
    return (u32)__cvta_generic_to_shared(p);
}

__device__ __forceinline__ void mma16816(float c[4], u32 a0, u32 a1, u32 a2, u32 a3,
                                         u32 b0, u32 b1) {
    asm volatile(
        "mma.sync.aligned.m16n8k16.row.col.f32.bf16.bf16.f32 "
        "{%0,%1,%2,%3}, {%4,%5,%6,%7}, {%8,%9}, {%0,%1,%2,%3};"
        : "+f"(c[0]), "+f"(c[1]), "+f"(c[2]), "+f"(c[3])
        : "r"(a0), "r"(a1), "r"(a2), "r"(a3), "r"(b0), "r"(b1));
}

// split v0,v1 into bf16 hi pair + lo (residual) pair
__device__ __forceinline__ void split_pack(float v0, float v1, u32& hi, u32& lo) {
    __nv_bfloat16 h0 = __float2bfloat16(v0), h1 = __float2bfloat16(v1);
    hi = (u32)__bfloat16_as_ushort(h0) | ((u32)__bfloat16_as_ushort(h1) << 16);
    __nv_bfloat16 l0 = __float2bfloat16(v0 - __bfloat162float(h0));
    __nv_bfloat16 l1 = __float2bfloat16(v1 - __bfloat162float(h1));
    lo = (u32)__bfloat16_as_ushort(l0) | ((u32)__bfloat16_as_ushort(l1) << 16);
}

// ---------- prep: pack all B operands fragment-ordered ----------
__global__ void prep_all(const float* __restrict__ W2, const float* __restrict__ Wf,
                         const float* __restrict__ Wd, const float* __restrict__ Wc1,
                         const float* __restrict__ Wc2) {
    int b = blockIdx.x;
    int lane = threadIdx.x;
    int kq = (lane & 3) * 2, nq = lane >> 2;
    float x0, x1, x2, x3;
    uint4* dst;
    if (b < 128) {  // W2 [128][128], ks=b>>4 nt=b&15
        int ks = b >> 4, nt = b & 15;
        int k0 = ks * 16 + kq, n = nt * 8 + nq;
        x0 = W2[k0 * 128 + n];
        x1 = W2[(k0 + 1) * 128 + n];
        x2 = W2[(k0 + 8) * 128 + n];
        x3 = W2[(k0 + 9) * 128 + n];
        dst = g_Bf + b * 32 + lane;
    } else if (b < 152) {  // feat: B = [Wf | Wd | 0], K=128 N=24
        int idx = b - 128, ks = idx / 3, nt = idx - ks * 3;
        int k0 = ks * 16 + kq, n = nt * 8 + nq;
        auto val = [&](int k) -> float {
            if (n < 16) return Wf[k * 16 + n];
            if (n == 16) return Wd[k];
            return 0.f;
        };
        x0 = val(k0); x1 = val(k0 + 1); x2 = val(k0 + 8); x3 = val(k0 + 9);
        dst = g_Bf + 4096 + idx * 32 + lane;
    } else if (b < 184) {  // c1: Wc1 [32][128], ks 0=feat rows,1=ynm rows
        int idx = b - 152, ks = idx >> 4, nt = idx & 15;
        int k0 = ks * 16 + kq, n = nt * 8 + nq;
        x0 = Wc1[k0 * 128 + n];
        x1 = Wc1[(k0 + 1) * 128 + n];
        x2 = Wc1[(k0 + 8) * 128 + n];
        x3 = Wc1[(k0 + 9) * 128 + n];
        dst = g_Bf + 4864 + idx * 32 + lane;
    } else {  // c2: B = [Wc2 | 0], K=128 N=8
        int ks = b - 184;
        int k0 = ks * 16 + kq, n = nq;
        auto val = [&](int k) -> float { return (n < 3) ? Wc2[k * 3 + n] : 0.f; };
        x0 = val(k0); x1 = val(k0 + 1); x2 = val(k0 + 8); x3 = val(k0 + 9);
        dst = g_Bf + 5888 + ks * 32 + lane;
    }
    uint4 v;
    split_pack(x0, x1, v.x, v.z);
    split_pack(x2, x3, v.y, v.w);
    *dst = v;
}

// ---------- main kernel ----------
// wsm layout (floats): W1 0..384, b1 384..512, b2 512..640, bc1 640..768,
// bf 768..784, bd 784, bc2 785..788
__global__ __launch_bounds__(128, 3) void radiance_kernel(
    const float* __restrict__ rays_o, const float* __restrict__ rays_d,
    const float* __restrict__ aabb,
    const float* __restrict__ W1, const float* __restrict__ b1,
    const float* __restrict__ W2, const float* __restrict__ b2,
    const float* __restrict__ Wd, const float* __restrict__ bd,
    const float* __restrict__ Wf, const float* __restrict__ bf,
    const float* __restrict__ Wc1, const float* __restrict__ bc1,
    const float* __restrict__ Wc2, const float* __restrict__ bc2,
    float* __restrict__ out) {
    extern __shared__ float sm[];
    float* wsm  = sm;            // 800
    float* sxyz = sm + 800;      // 192
    float* sts  = sm + 992;      // 64
    float* ssig = sm + 1056;     // 64
    float* sins = sm + 1120;     // 64
    float* synm = sm + 1184;     // 16
    float* sc0  = sm + 1200;     // 64
    float* sc1  = sm + 1264;     // 64
    float* sc2  = sm + 1328;     // 64
    float* sred = sm + 1392;     // 16

    const int tid = threadIdx.x;
    const int ray = blockIdx.x;
    const int wid = tid >> 5;
    const int lane = tid & 31;
    const int pb = wid * 16;
    const int r0 = lane >> 2;
    const int p0 = pb + r0, p1 = p0 + 8;
    const int kq = (lane & 3) * 2;

    // ---- stage small weights ----
    {
        u32 wu = smem_u32(wsm);
        if (tid < 96) cpa16(wu + tid * 16u, W1 + tid * 4);
        else cpa16(wu + 1536u + (tid - 96) * 16u, b1 + (tid - 96) * 4);
        if (tid < 32) cpa16(wu + 2048u + tid * 16u, b2 + tid * 4);
        else if (tid < 64) cpa16(wu + 2560u + (tid - 32) * 16u, bc1 + (tid - 32) * 4);
        else if (tid < 68) cpa16(wu + 3072u + (tid - 64) * 16u, bf + (tid - 64) * 4);
        cpa_commit();
        if (tid == 68) wsm[784] = __ldg(bd);
        if (tid >= 69 && tid < 72) wsm[785 + tid - 69] = __ldg(bc2 + tid - 69);
    }

    // ---- ray setup ----
    float ox = rays_o[ray * 3 + 0], oy = rays_o[ray * 3 + 1], oz = rays_o[ray * 3 + 2];
    float dx = rays_d[ray * 3 + 0], dy = rays_d[ray * 3 + 1], dz = rays_d[ray * 3 + 2];
    float a0x = aabb[0], a0y = aabb[1], a0z = aabb[2];
    float a1x = aabb[3], a1y = aabb[4], a1z = aabb[5];
    float ix = 1.f / dx, iy = 1.f / dy, iz = 1.f / dz;
    float t1x = (a0x - ox) * ix, t2x = (a1x - ox) * ix;
    float t1y = (a0y - oy) * iy, t2y = (a1y - oy) * iy;
    float t1z = (a0z - oz) * iz, t2z = (a1z - oz) * iz;
    float tn = fmaxf(fmaxf(fminf(t1x, t2x), fminf(t1y, t2y)), fminf(t1z, t2z));
    tn = fmaxf(tn, 0.f);
    float tf = fminf(fminf(fmaxf(t1x, t2x), fmaxf(t1y, t2y)), fmaxf(t1z, t2z));
    tf = fminf(tf, 10.f);
    bool active = tn < tf;
    if (!active) { tn = 0.f; tf = 1.f; }
    float dnorm = sqrtf(dx * dx + dy * dy + dz * dz);

    if (tid == 0) {
        float inv = 1.f / dnorm;
        float x = dx * inv, y = dy * inv, z = dz * inv;
        float x2 = x * x, y2 = y * y, z2 = z * z;
        synm[0]  = 0.282094791773878f;
        synm[1]  = -0.488602511902920f * y;
        synm[2]  = 0.488602511902920f * z;
        synm[3]  = -0.488602511902920f * x;
        synm[4]  = 1.092548430592079f * x * y;
        synm[5]  = -1.092548430592079f * y * z;
        synm[6]  = 0.315391565252520f * (3.0f * z2 - 1.0f);
        synm[7]  = -1.092548430592079f * x * z;
        synm[8]  = 0.546274215296040f * (x2 - y2);
        synm[9]  = -0.590043589926644f * y * (3.0f * x2 - y2);
        synm[10] = 2.890611442640554f * x * y * z;
        synm[11] = -0.457045799464466f * y * (5.0f * z2 - 1.0f);
        synm[12] = 0.373176332590115f * z * (5.0f * z2 - 3.0f);
        synm[13] = -0.457045799464466f * x * (5.0f * z2 - 1.0f);
        synm[14] = 1.445305721320277f * z * (x2 - y2);
        synm[15] = -0.590043589926644f * x * (x2 - 3.0f * y2);
    }
    if (tid < 64) {
        float fr = (tid + 0.5f) * (1.f / 64.f);
        float t = tn + fr * (tf - tn);
        sts[tid] = t;
        float px = fmaf(dx, t, ox), py = fmaf(dy, t, oy), pz = fmaf(dz, t, oz);
        float nx = (px - a0x) / (a1x - a0x) * 2.f - 1.f;
        float ny = (py - a0y) / (a1y - a0y) * 2.f - 1.f;
        float nz = (pz - a0z) / (a1z - a0z) * 2.f - 1.f;
        sxyz[tid * 3 + 0] = nx;
        sxyz[tid * 3 + 1] = ny;
        sxyz[tid * 3 + 2] = nz;
        bool inside = (nx >= -1.f) && (nx <= 1.f) && (ny >= -1.f) && (ny <= 1.f) &&
                      (nz >= -1.f) && (nz <= 1.f);
        sins[tid] = inside ? 1.f : 0.f;
    }
    cpa_wait<0>();
    __syncthreads();  // (1)

    // ======== layer 2 (W2) via HMMA: c[16][4] = h1 @ W2 ========
    float c[16][4];
#pragma unroll
    for (int nt = 0; nt < 16; nt++)
#pragma unroll
        for (int i = 0; i < 4; i++) c[nt][i] = 0.f;
    {
        float P0x = sxyz[p0 * 3], P0y = sxyz[p0 * 3 + 1], P0z = sxyz[p0 * 3 + 2];
        float P1x = sxyz[p1 * 3], P1y = sxyz[p1 * 3 + 1], P1z = sxyz[p1 * 3 + 2];
#pragma unroll 1
        for (int ks = 0; ks < 8; ks++) {
            int j0 = ks * 16 + kq;
            float v[8];
#pragma unroll
            for (int q = 0; q < 4; q++) {
                int j = j0 + (q & 1) + (q >> 1) * 8;
                float w0 = wsm[j], w1 = wsm[128 + j], w2 = wsm[256 + j], bb = wsm[384 + j];
                float h0 = fmaf(P0x, w0, bb);
                h0 = fmaf(P0y, w1, h0);
                h0 = fmaf(P0z, w2, h0);
                float h1v = fmaf(P1x, w0, bb);
                h1v = fmaf(P1y, w1, h1v);
                h1v = fmaf(P1z, w2, h1v);
                v[q] = fmaxf(h0, 0.f);
                v[4 + q] = fmaxf(h1v, 0.f);
            }
            u32 ahi[4], alo[4];
            split_pack(v[0], v[1], ahi[0], alo[0]);   // p0, k low
            split_pack(v[4], v[5], ahi[1], alo[1]);   // p1, k low
            split_pack(v[2], v[3], ahi[2], alo[2]);   // p0, k high
            split_pack(v[6], v[7], ahi[3], alo[3]);   // p1, k high
            const uint4* gb = g_Bf + ks * 16 * 32 + lane;
#pragma unroll
            for (int nt = 0; nt < 16; nt++) {
                uint4 B = __ldg(gb + nt * 32);
                mma16816(c[nt], ahi[0], ahi[1], ahi[2], ahi[3], B.x, B.y);
                mma16816(c[nt], ahi[0], ahi[1], ahi[2], ahi[3], B.z, B.w);
                mma16816(c[nt], alo[0], alo[1], alo[2], alo[3], B.x, B.y);
            }
        }
    }

    // ======== feat/sigma GEMM: cf[3][4] = h2 @ [Wf|Wd|0], K=128 N=24 ========
    float cf[3][4];
#pragma unroll
    for (int nt = 0; nt < 3; nt++)
#pragma unroll
        for (int i = 0; i < 4; i++) cf[nt][i] = 0.f;
#pragma unroll 1
    for (int ks = 0; ks < 8; ks++) {
        int col = ks * 16 + kq;
        float b20 = wsm[512 + col], b21 = wsm[512 + col + 1];
        float b28 = wsm[512 + col + 8], b29 = wsm[512 + col + 9];
        u32 ahi[4], alo[4];
        split_pack(fmaxf(c[2 * ks][0] + b20, 0.f), fmaxf(c[2 * ks][1] + b21, 0.f),
                   ahi[0], alo[0]);
        split_pack(fmaxf(c[2 * ks][2] + b20, 0.f), fmaxf(c[2 * ks][3] + b21, 0.f),
                   ahi[1], alo[1]);
        split_pack(fmaxf(c[2 * ks + 1][0] + b28, 0.f), fmaxf(c[2 * ks + 1][1] + b29, 0.f),
                   ahi[2], alo[2]);
        split_pack(fmaxf(c[2 * ks + 1][2] + b28, 0.f), fmaxf(c[2 * ks + 1][3] + b29, 0.f),
                   ahi[3], alo[3]);
        const uint4* gb = g_Bf + 4096 + ks * 3 * 32 + lane;
#pragma unroll
        for (int nt = 0; nt < 3; nt++) {
            uint4 B = __ldg(gb + nt * 32);
            mma16816(cf[nt], ahi[0], ahi[1], ahi[2], ahi[3], B.x, B.y);
            mma16816(cf[nt], ahi[0], ahi[1], ahi[2], ahi[3], B.z, B.w);
            mma16816(cf[nt], alo[0], alo[1], alo[2], alo[3], B.x, B.y);
        }
    }
    // sigma = exp(col16 + bd) * inside   (col16 held by lanes with kq==0)
    if ((lane & 3) == 0) {
        float bdv = wsm[784];
        ssig[p0] = expf(cf[2][0] + bdv) * sins[p0];
        ssig[p1] = expf(cf[2][2] + bdv) * sins[p1];
    }

    // ======== c1 GEMM: cc[16][4] = [feat|ynm] @ Wc1, K=32 N=128 ========
    u32 fhi[4], flo[4], yhi0, ylo0, yhi2, ylo2;
    {
        float bf0 = wsm[768 + kq], bf1 = wsm[768 + kq + 1];
        float bf8 = wsm[768 + kq + 8], bf9 = wsm[768 + kq + 9];
        split_pack(cf[0][0] + bf0, cf[0][1] + bf1, fhi[0], flo[0]);  // p0, k low
        split_pack(cf[0][2] + bf0, cf[0][3] + bf1, fhi[1], flo[1]);  // p1, k low
        split_pack(cf[1][0] + bf8, cf[1][1] + bf9, fhi[2], flo[2]);  // p0, k high
        split_pack(cf[1][2] + bf8, cf[1][3] + bf9, fhi[3], flo[3]);  // p1, k high
        split_pack(synm[kq], synm[kq + 1], yhi0, ylo0);              // all rows equal
        split_pack(synm[kq + 8], synm[kq + 9], yhi2, ylo2);
    }
    float cc[16][4];
#pragma unroll
    for (int nt = 0; nt < 16; nt++)
#pragma unroll
        for (int i = 0; i < 4; i++) cc[nt][i] = 0.f;
#pragma unroll 1
    for (int nt = 0; nt < 16; nt++) {
        uint4 Bf = __ldg(g_Bf + 4864 + nt * 32 + lane);          // ks=0 (feat rows)
        mma16816(cc[nt], fhi[0], fhi[1], fhi[2], fhi[3], Bf.x, Bf.y);
        mma16816(cc[nt], fhi[0], fhi[1], fhi[2], fhi[3], Bf.z, Bf.w);
        mma16816(cc[nt], flo[0], flo[1], flo[2], flo[3], Bf.x, Bf.y);
        uint4 By = __ldg(g_Bf + 4864 + (16 + nt) * 32 + lane);   // ks=1 (ynm rows)
        mma16816(cc[nt], yhi0, yhi0, yhi2, yhi2, By.x, By.y);
        mma16816(cc[nt], yhi0, yhi0, yhi2, yhi2, By.z, By.w);
        mma16816(cc[nt], ylo0, ylo0, ylo2, ylo2, By.x, By.y);
    }

    // ======== c2 GEMM: ccol[4] = relu(hc) @ [Wc2|0], K=128 N=8 ========
    float ccol[4] = {0.f, 0.f, 0.f, 0.f};
#pragma unroll 1
    for (int ks = 0; ks < 8; ks++) {
        int col = ks * 16 + kq;
        float bb0 = wsm[640 + col], bb1 = wsm[640 + col + 1];
        float bb8 = wsm[640 + col + 8], bb9 = wsm[640 + col + 9];
        u32 ahi[4], alo[4];
        split_pack(fmaxf(cc[2 * ks][0] + bb0, 0.f), fmaxf(cc[2 * ks][1] + bb1, 0.f),
                   ahi[0], alo[0]);
        split_pack(fmaxf(cc[2 * ks][2] + bb0, 0.f), fmaxf(cc[2 * ks][3] + bb1, 0.f),
                   ahi[1], alo[1]);
        split_pack(fmaxf(cc[2 * ks + 1][0] + bb8, 0.f), fmaxf(cc[2 * ks + 1][1] + bb9, 0.f),
                   ahi[2], alo[2]);
        split_pack(fmaxf(cc[2 * ks + 1][2] + bb8, 0.f), fmaxf(cc[2 * ks + 1][3] + bb9, 0.f),
                   ahi[3], alo[3]);
        uint4 B = __ldg(g_Bf + 5888 + ks * 32 + lane);
        mma16816(ccol, ahi[0], ahi[1], ahi[2], ahi[3], B.x, B.y);
        mma16816(ccol, ahi[0], ahi[1], ahi[2], ahi[3], B.z, B.w);
        mma16816(ccol, alo[0], alo[1], alo[2], alo[3], B.x, B.y);
    }
    // color writeback: lanes kq==0 hold cols 0,1; kq==2 (lane&3==1) hold col 2
    {
        int cq = lane & 3;
        if (cq == 0) {
            float b0v = wsm[785], b1v = wsm[786];
            sc0[p0] = 1.f / (1.f + expf(-(ccol[0] + b0v)));
            sc1[p0] = 1.f / (1.f + expf(-(ccol[1] + b1v)));
            sc0[p1] = 1.f / (1.f + expf(-(ccol[2] + b0v)));
            sc1[p1] = 1.f / (1.f + expf(-(ccol[3] + b1v)));
        } else if (cq == 1) {
            float b2v = wsm[787];
            sc2[p0] = 1.f / (1.f + expf(-(ccol[0] + b2v)));
            sc2[p1] = 1.f / (1.f + expf(-(ccol[2] + b2v)));
        }
    }
    __syncthreads();  // (2) ssig, sc0-2 visible

    // ======== integration ========
    const int wrp = tid >> 5;
    float tau = 0.f, tcur = 0.f, sc = 0.f;
    if (wrp < 2) {
        tcur = sts[tid];
        float tnext = (tid < 63) ? sts[tid + 1] : (tf + 1.0f);  // BOOSTER = 1.0
        tau = ssig[tid] * (tnext - tcur) * dnorm;
        sc = tau;
#pragma unroll
        for (int off = 1; off < 32; off <<= 1) {
            float u = __shfl_up_sync(0xffffffffu, sc, off);
            if (lane >= off) sc += u;
        }
        if (wrp == 0 && lane == 31) sred[15] = sc;
    }
    __syncthreads();  // (3)
    if (wrp < 2) {
        if (wrp == 1) sc += sred[15];
        float excl = sc - tau;
        float wgt = expf(-excl) * (1.f - expf(-tau));
        float v0 = wgt * sc0[tid];
        float v1 = wgt * sc1[tid];
        float v2 = wgt * sc2[tid];
        float v3 = wgt;
        float v4 = wgt * tcur;
#pragma unroll
        for (int off = 16; off >= 1; off >>= 1) {
            v0 += __shfl_xor_sync(0xffffffffu, v0, off);
            v1 += __shfl_xor_sync(0xffffffffu, v1, off);
            v2 += __shfl_xor_sync(0xffffffffu, v2, off);
            v3 += __shfl_xor_sync(0xffffffffu, v3, off);
            v4 += __shfl_xor_sync(0xffffffffu, v4, off);
        }
        if (lane == 0) {
            sred[wrp * 5 + 0] = v0;
            sred[wrp * 5 + 1] = v1;
            sred[wrp * 5 + 2] = v2;
            sred[wrp * 5 + 3] = v3;
            sred[wrp * 5 + 4] = v4;
        }
    }
    __syncthreads();  // (4)
    if (tid < 5) {
        float am = active ? 1.f : 0.f;
        out[ray * 5 + tid] = (sred[tid] + sred[5 + tid]) * am;
    }
}

extern "C" void kernel_launch(void* const* d_in, const int* in_sizes, int n_in,
                              void* d_out, int out_size) {
    const float* rays_o = (const float*)d_in[0];
    const float* rays_d = (const float*)d_in[1];
    const float* aabb   = (const float*)d_in[2];
    const float* W1  = (const float*)d_in[3];
    const float* b1  = (const float*)d_in[4];
    const float* W2  = (const float*)d_in[5];
    const float* b2  = (const float*)d_in[6];
    const float* Wd  = (const float*)d_in[7];
    const float* bd  = (const float*)d_in[8];
    const float* Wf  = (const float*)d_in[9];
    const float* bf  = (const float*)d_in[10];
    const float* Wc1 = (const float*)d_in[11];
    const float* bc1 = (const float*)d_in[12];
    const float* Wc2 = (const float*)d_in[13];
    const float* bc2 = (const float*)d_in[14];
    float* out = (float*)d_out;

    int n_rays = in_sizes[0] / 3;
    prep_all<<<192, 32>>>(W2, Wf, Wd, Wc1, Wc2);
    size_t smem = 1408 * sizeof(float);  // 5632 B
    radiance_kernel<<<n_rays, 128, smem>>>(rays_o, rays_d, aabb, W1, b1, W2, b2, Wd, bd,
                                           Wf, bf, Wc1, bc1, Wc2, bc2, out);
}